// round 7
// baseline (speedup 1.0000x reference)
#include <cuda_runtime.h>
#include <cuda_bf16.h>
#include <cstdint>

#define B_    16
#define CIN   512
#define COUT  512
#define DLAT  512
#define Hs    64
#define Ws    64
#define NPIX  (Hs*Ws)

#define LIN_COEF  0.04419417382415922f    // 1/sqrt(512)
#define CONV_COEF 0.014731391274719742f   // 1/sqrt(512*9)

// ---------------- device scratch (no allocation allowed) ----------------
__device__ float g_mod[B_ * CIN];
__device__ float g_sig[B_ * COUT];
__device__ float g_cwt[CIN * 9 * COUT];
__device__ float g_wsqT[CIN * COUT];
__device__ __nv_bfloat16 g_xh[(size_t)B_ * NPIX * CIN];   // NHWC hi
__device__ __nv_bfloat16 g_xl[(size_t)B_ * NPIX * CIN];   // NHWC lo
__device__ __nv_bfloat16 g_wh[9 * COUT * CIN];            // [tap][o][i] hi
__device__ __nv_bfloat16 g_wl[9 * COUT * CIN];            // [tap][o][i] lo

__device__ __forceinline__ uint32_t smem_u32(const void* p) {
    uint32_t a;
    asm("{ .reg .u64 t; cvta.to.shared.u64 t, %1; cvt.u32.u64 %0, t; }"
        : "=r"(a) : "l"(p));
    return a;
}

// ============================================================
// KP1: style (bid<32) + conv_w transpose (bid<9248) + wsplit (bid<9760)
// block 256
// ============================================================
__global__ __launch_bounds__(256) void kp1(
    const float* __restrict__ w, const float* __restrict__ sw,
    const float* __restrict__ sb, const float* __restrict__ cw)
{
    int bid = blockIdx.x;
    if (bid < 32) {
        __shared__ float s_sw[16][DLAT + 1];
        int i0 = bid * 16;
        for (int idx = threadIdx.x; idx < 16 * DLAT; idx += 256) {
            int r = idx / DLAT, d = idx % DLAT;
            s_sw[r][d] = sw[(i0 + r) * DLAT + d];
        }
        __syncthreads();
        int t = threadIdx.x;
        int b = t >> 4, il = t & 15;
        const float* wb = w + b * DLAT;
        float acc = 0.f;
        for (int d = 0; d < DLAT; d++) acc += __ldg(&wb[d]) * s_sw[il][d];
        int i = i0 + il;
        g_mod[b * CIN + i] = (acc * LIN_COEF + sb[i]) * CONV_COEF;
    } else if (bid < 32 + 9216) {
        int e = (bid - 32) * 256 + threadIdx.x;       // (i, tap, o), o fastest
        int o = e & 511;
        int r = e >> 9;
        int tap = r % 9, i = r / 9;
        g_cwt[(i * 9 + tap) * COUT + o] = cw[(o * CIN + i) * 9 + tap];
    } else {
        int o = bid - 9248;
        for (int i = threadIdx.x; i < CIN; i += 256) {
            const float* p = cw + ((size_t)o * CIN + i) * 9;
#pragma unroll
            for (int tap = 0; tap < 9; tap++) {
                float v = p[tap];
                __nv_bfloat16 h = __float2bfloat16(v);
                __nv_bfloat16 l = __float2bfloat16(v - __bfloat162float(h));
                size_t di = ((size_t)tap * COUT + o) * CIN + i;
                g_wh[di] = h;
                g_wl[di] = l;
            }
        }
    }
}

// ============================================================
// KP2: wsq (bid<512) + xsplit (bid<8704), block 512
// ============================================================
__global__ __launch_bounds__(512) void kp2(const float* __restrict__ x)
{
    int bid = blockIdx.x;
    if (bid < 512) {
        int i = bid, o = threadIdx.x;
        float s = 0.f;
#pragma unroll
        for (int tap = 0; tap < 9; tap++) {
            float v = g_cwt[(i * 9 + tap) * COUT + o];
            s += v * v;
        }
        g_wsqT[i * COUT + o] = s;
    } else {
        __shared__ float t[64][65];
        int q = bid - 512;
        int p0 = (q & 63) * 64;
        int i0 = ((q >> 6) & 7) * 64;
        int b  = q >> 9;
        for (int idx = threadIdx.x; idx < 4096; idx += 512) {
            int ii = idx >> 6, pp = idx & 63;
            t[ii][pp] = x[((size_t)b * CIN + i0 + ii) * NPIX + p0 + pp] *
                        g_mod[b * CIN + i0 + ii];
        }
        __syncthreads();
        for (int idx = threadIdx.x; idx < 4096; idx += 512) {
            int pp = idx >> 6, ii = idx & 63;
            float v = t[ii][pp];
            __nv_bfloat16 h = __float2bfloat16(v);
            __nv_bfloat16 l = __float2bfloat16(v - __bfloat162float(h));
            size_t di = ((size_t)b * NPIX + p0 + pp) * CIN + i0 + ii;
            g_xh[di] = h;
            g_xl[di] = l;
        }
    }
}

// ============================================================
// KP3: sigma_inv, 16 blocks x 512
// ============================================================
__global__ __launch_bounds__(512) void kp3()
{
    __shared__ float m2[CIN];
    int b = blockIdx.x, o = threadIdx.x;
    for (int i = threadIdx.x; i < CIN; i += 512) {
        float m = g_mod[b * CIN + i];
        m2[i] = m * m;
    }
    __syncthreads();
    float s = 0.f;
    for (int i = 0; i < CIN; i++) s += m2[i] * g_wsqT[i * COUT + o];
    g_sig[b * COUT + o] = 1.0f / sqrtf(s + 1e-8f);
}

// ============================================================
// K6: conv as bf16 3-pass split GEMM, halo-resident B.
// CTA 128oc x 256px, 512 thr, warp grid 4(M)x4(N), warp tile 32oc x 64px.
// B: one 64-ic chunk halo (6x66, 2 planes) resident for 9 taps.
// A: per-(tap,ic) stage, triple-buffered cp.async.
// Pass order per kk: (Ah,Bh),(Al,Bh) then reload bF with Bl: (Ah,Bl)
// -> live regs ~121, no spills under 512-thread launch bounds.
// ============================================================
#define BH_ROWS 6
#define BH_COLS 66
#define BH_PX   (BH_ROWS * BH_COLS)      // 396
#define BPL     (BH_PX * 128)            // 50688 per plane
#define A_STG   32768                    // per A stage (2 planes x 16KB)
#define B_OFF   (3 * A_STG)              // 98304
#define DSMEM   (B_OFF + 2 * BPL)        // 199680

#define MMA_BF16(c, a, b0, b1)                                               \
    asm volatile("mma.sync.aligned.m16n8k16.row.col.f32.bf16.bf16.f32 "      \
        "{%0,%1,%2,%3}, {%4,%5,%6,%7}, {%8,%9}, {%0,%1,%2,%3};"              \
        : "+f"((c)[0]), "+f"((c)[1]), "+f"((c)[2]), "+f"((c)[3])             \
        : "r"((a)[0]), "r"((a)[1]), "r"((a)[2]), "r"((a)[3]),                \
          "r"(b0), "r"(b1))

#define LDSM4(r, addr)                                                       \
    asm volatile("ldmatrix.sync.aligned.m8n8.x4.shared.b16 "                 \
        "{%0,%1,%2,%3}, [%4];"                                               \
        : "=r"((r)[0]), "=r"((r)[1]), "=r"((r)[2]), "=r"((r)[3])             \
        : "r"(addr))

__global__ __launch_bounds__(512, 1) void k_conv_hmma(
    const float* __restrict__ noise, const float* __restrict__ scale_noise,
    const float* __restrict__ bias, float* __restrict__ out)
{
    extern __shared__ __align__(1024) char dsm[];
    uint32_t sbase = smem_u32(dsm);

    int tid = threadIdx.x;
    int lane = tid & 31, wid = tid >> 5;
    int wm = wid >> 2, wn = wid & 3;
    int b    = blockIdx.z;
    int oc0  = blockIdx.x * 128;
    int pix0 = blockIdx.y * 256;
    int pr0  = blockIdx.y * 4;

    // A ldmatrix lane components
    int selA = ((lane >> 4) & 1) * 16;
    uint32_t rbA[2], mkA[2];
#pragma unroll
    for (int mt = 0; mt < 2; mt++) {
        int row = wm * 32 + mt * 16 + (lane & 15);
        rbA[mt] = row * 128;
        mkA[mt] = (uint32_t)(row & 7) << 4;
    }
    // B lane pixel decomposition
    int selB = ((lane >> 3) & 1) * 16;
    int irB[4], icB[4];
#pragma unroll
    for (int j = 0; j < 4; j++) {
        int n = wn * 64 + j * 16 + (lane & 7) + ((lane >> 4) & 1) * 8;
        irB[j] = n >> 6;
        icB[j] = n & 63;
    }

    float acc[2][8][4];
#pragma unroll
    for (int mt = 0; mt < 2; mt++)
#pragma unroll
        for (int nt = 0; nt < 8; nt++)
#pragma unroll
            for (int q = 0; q < 4; q++) acc[mt][nt][q] = 0.f;

    auto load_A = [&](int tapv, int icv, int buf) {
#pragma unroll
        for (int k = 0; k < 4; k++) {
            int idx = tid + k * 512;
            int plane = idx >> 10;
            int rem = idx & 1023;
            int row = rem >> 3, cb = rem & 7;
            const __nv_bfloat16* g = (plane ? g_wl : g_wh) +
                ((size_t)tapv * COUT + oc0 + row) * CIN + icv * 64 + cb * 8;
            uint32_t d = sbase + buf * A_STG + plane * 16384 +
                         (uint32_t)(row * 128) + (uint32_t)((cb * 16) ^ ((row & 7) << 4));
            asm volatile("cp.async.cg.shared.global [%0], [%1], 16;"
                         :: "r"(d), "l"(g));
        }
        asm volatile("cp.async.commit_group;");
    };

    auto load_B = [&](int icv) {
        for (int idx = tid; idx < BH_PX * 8; idx += 512) {
            int px = idx >> 3, cb = idx & 7;
            int hrow = px / BH_COLS;
            int hcol = px - hrow * BH_COLS;
            int r = pr0 - 1 + hrow;
            int c = hcol - 1;
            int ok = ((unsigned)r < Hs) && ((unsigned)c < Ws);
            size_t gofs = ((size_t)b * NPIX + (ok ? r * Ws + c : 0)) * CIN +
                          icv * 64 + cb * 8;
            uint32_t dofs = (uint32_t)(px * 128) +
                            (uint32_t)((cb * 16) ^ ((px & 7) << 4));
            int sz = ok ? 16 : 0;
            {
                uint32_t d = sbase + B_OFF + dofs;
                const __nv_bfloat16* g = g_xh + gofs;
                asm volatile("cp.async.cg.shared.global [%0], [%1], 16, %2;"
                             :: "r"(d), "l"(g), "r"(sz));
            }
            {
                uint32_t d = sbase + B_OFF + BPL + dofs;
                const __nv_bfloat16* g = g_xl + gofs;
                asm volatile("cp.async.cg.shared.global [%0], [%1], 16, %2;"
                             :: "r"(d), "l"(g), "r"(sz));
            }
        }
        asm volatile("cp.async.commit_group;");
    };

    // prologue: B(0), A(0), A(1)  (3 commit groups)
    load_B(0);
    load_A(0, 0, 0);
    load_A(1, 0, 1);

    int s = 0;
    int ntap = 2, nic = 0;
    for (int ic = 0; ic < 8; ic++) {
        for (int tap = 0; tap < 9; tap++, s++) {
            if (s == 71)
                asm volatile("cp.async.wait_group 0;");
            else
                asm volatile("cp.async.wait_group 1;");
            __syncthreads();

            if (tap == 0 && ic > 0) {
                // B first (so the following wait forces it), then A prefetch
                load_B(ic);
                if (s < 70) {
                    load_A(ntap, nic, (s + 2) % 3);
                    if (++ntap == 9) { ntap = 0; nic++; }
                }
                asm volatile("cp.async.wait_group 1;");   // completes B, leaves A
                __syncthreads();
            } else if (s < 70) {
                load_A(ntap, nic, (s + 2) % 3);
                if (++ntap == 9) { ntap = 0; nic++; }
            }

            // ---- compute stage s ----
            uint32_t abuf = sbase + (s % 3) * A_STG;
            int dy = tap / 3 - 1, dx = tap % 3 - 1;
            uint32_t rowB[4], mskB[4];
#pragma unroll
            for (int j = 0; j < 4; j++) {
                int rp = (irB[j] + 1 + dy) * BH_COLS + icB[j] + 1 + dx;
                rowB[j] = (uint32_t)(rp * 128);
                mskB[j] = (uint32_t)(rp & 7) << 4;
            }

#pragma unroll
            for (int kk = 0; kk < 4; kk++) {
                int col = kk * 32;
                uint32_t aF[2][2][4];
#pragma unroll
                for (int pl = 0; pl < 2; pl++)
#pragma unroll
                    for (int mt = 0; mt < 2; mt++) {
                        uint32_t a = abuf + pl * 16384 + rbA[mt] +
                                     (uint32_t)((col + selA) ^ mkA[mt]);
                        LDSM4(aF[pl][mt], a);
                    }
                uint32_t bF[4][4];
                // Bh fragments
#pragma unroll
                for (int j = 0; j < 4; j++) {
                    uint32_t a = sbase + B_OFF + rowB[j] +
                                 (uint32_t)((col + selB) ^ mskB[j]);
                    LDSM4(bF[j], a);
                }
                // pass hh: Ah x Bh
#pragma unroll
                for (int mt = 0; mt < 2; mt++)
#pragma unroll
                    for (int nt = 0; nt < 8; nt++) {
                        int j = nt >> 1, lo = (nt & 1) * 2;
                        MMA_BF16(acc[mt][nt], aF[0][mt], bF[j][lo], bF[j][lo + 1]);
                    }
                // pass lh: Al x Bh
#pragma unroll
                for (int mt = 0; mt < 2; mt++)
#pragma unroll
                    for (int nt = 0; nt < 8; nt++) {
                        int j = nt >> 1, lo = (nt & 1) * 2;
                        MMA_BF16(acc[mt][nt], aF[1][mt], bF[j][lo], bF[j][lo + 1]);
                    }
                // Bl fragments (reuse bF regs)
#pragma unroll
                for (int j = 0; j < 4; j++) {
                    uint32_t a = sbase + B_OFF + BPL + rowB[j] +
                                 (uint32_t)((col + selB) ^ mskB[j]);
                    LDSM4(bF[j], a);
                }
                // pass hl: Ah x Bl
#pragma unroll
                for (int mt = 0; mt < 2; mt++)
#pragma unroll
                    for (int nt = 0; nt < 8; nt++) {
                        int j = nt >> 1, lo = (nt & 1) * 2;
                        MMA_BF16(acc[mt][nt], aF[0][mt], bF[j][lo], bF[j][lo + 1]);
                    }
            }
        }
    }

    // ---------------- epilogue ----------------
    float sn = __ldg(scale_noise);
#pragma unroll
    for (int mt = 0; mt < 2; mt++) {
        int oc_lo = oc0 + wm * 32 + mt * 16 + (lane >> 2);
        float sg0 = g_sig[b * COUT + oc_lo];
        float sg1 = g_sig[b * COUT + oc_lo + 8];
        float bi0 = __ldg(&bias[oc_lo]);
        float bi1 = __ldg(&bias[oc_lo + 8]);
#pragma unroll
        for (int nt = 0; nt < 8; nt++) {
            int p = pix0 + wn * 64 + nt * 8 + (lane & 3) * 2;
            float2 nz = *(const float2*)&noise[(size_t)b * NPIX + p];
            float n0 = sn * nz.x, n1 = sn * nz.y;

            float v0 = acc[mt][nt][0] * sg0 + n0 + bi0;
            float v1 = acc[mt][nt][1] * sg0 + n1 + bi0;
            float v2 = acc[mt][nt][2] * sg1 + n0 + bi1;
            float v3 = acc[mt][nt][3] * sg1 + n1 + bi1;
            v0 = v0 < 0.f ? 0.2f * v0 : v0;
            v1 = v1 < 0.f ? 0.2f * v1 : v1;
            v2 = v2 < 0.f ? 0.2f * v2 : v2;
            v3 = v3 < 0.f ? 0.2f * v3 : v3;

            *(float2*)&out[((size_t)(b * COUT + oc_lo)) * NPIX + p] =
                make_float2(v0, v1);
            *(float2*)&out[((size_t)(b * COUT + oc_lo + 8)) * NPIX + p] =
                make_float2(v2, v3);
        }
    }
}

// ============================================================
// launch: x, w, noise, style_w, style_b, conv_w, scale_noise, bias
// 4 launches total: kp1, kp2, kp3, conv
// ============================================================
extern "C" void kernel_launch(void* const* d_in, const int* in_sizes, int n_in,
                              void* d_out, int out_size)
{
    const float* x           = (const float*)d_in[0];
    const float* w           = (const float*)d_in[1];
    const float* noise       = (const float*)d_in[2];
    const float* style_w     = (const float*)d_in[3];
    const float* style_b     = (const float*)d_in[4];
    const float* conv_w      = (const float*)d_in[5];
    const float* scale_noise = (const float*)d_in[6];
    const float* bias        = (const float*)d_in[7];
    float* out = (float*)d_out;

    cudaFuncSetAttribute(k_conv_hmma,
                         cudaFuncAttributeMaxDynamicSharedMemorySize, DSMEM);

    kp1<<<9760, 256>>>(w, style_w, style_b, conv_w);
    kp2<<<8704, 512>>>(x);
    kp3<<<16, 512>>>();
    k_conv_hmma<<<dim3(4, 16, B_), 512, DSMEM>>>(noise, scale_noise, bias, out);
}

// round 8
// speedup vs baseline: 1.4108x; 1.4108x over previous
#include <cuda_runtime.h>
#include <cuda_fp16.h>
#include <cstdint>

#define B_    16
#define CIN   512
#define COUT  512
#define DLAT  512
#define Hs    64
#define Ws    64
#define NPIX  (Hs*Ws)

#define LIN_COEF  0.04419417382415922f    // 1/sqrt(512)
#define CONV_COEF 0.014731391274719742f   // 1/sqrt(512*9)

// ---------------- device scratch (no allocation allowed) ----------------
__device__ float g_mod[B_ * CIN];
__device__ float g_sig[B_ * COUT];
__device__ float g_cwt[CIN * 9 * COUT];
__device__ float g_wsqT[CIN * COUT];
__device__ __half g_xh[(size_t)B_ * NPIX * CIN];   // NHWC, fp16(x*mod)
__device__ __half g_wh[9 * COUT * CIN];            // [tap][o][i] fp16 hi
__device__ __half g_wl[9 * COUT * CIN];            // [tap][o][i] fp16 lo

__device__ __forceinline__ uint32_t smem_u32(const void* p) {
    uint32_t a;
    asm("{ .reg .u64 t; cvta.to.shared.u64 t, %1; cvt.u32.u64 %0, t; }"
        : "=r"(a) : "l"(p));
    return a;
}

// ============================================================
// KP1: style (bid<32) + conv_w transpose (bid<9248) + wsplit (bid<9760)
// ============================================================
__global__ __launch_bounds__(256) void kp1(
    const float* __restrict__ w, const float* __restrict__ sw,
    const float* __restrict__ sb, const float* __restrict__ cw)
{
    int bid = blockIdx.x;
    if (bid < 32) {
        __shared__ float s_sw[16][DLAT + 1];
        int i0 = bid * 16;
        for (int idx = threadIdx.x; idx < 16 * DLAT; idx += 256) {
            int r = idx / DLAT, d = idx % DLAT;
            s_sw[r][d] = sw[(i0 + r) * DLAT + d];
        }
        __syncthreads();
        int t = threadIdx.x;
        int b = t >> 4, il = t & 15;
        const float* wb = w + b * DLAT;
        float acc = 0.f;
        for (int d = 0; d < DLAT; d++) acc += __ldg(&wb[d]) * s_sw[il][d];
        int i = i0 + il;
        g_mod[b * CIN + i] = (acc * LIN_COEF + sb[i]) * CONV_COEF;
    } else if (bid < 32 + 9216) {
        int e = (bid - 32) * 256 + threadIdx.x;       // (i, tap, o), o fastest
        int o = e & 511;
        int r = e >> 9;
        int tap = r % 9, i = r / 9;
        g_cwt[(i * 9 + tap) * COUT + o] = cw[(o * CIN + i) * 9 + tap];
    } else {
        int o = bid - 9248;
        for (int i = threadIdx.x; i < CIN; i += 256) {
            const float* p = cw + ((size_t)o * CIN + i) * 9;
#pragma unroll
            for (int tap = 0; tap < 9; tap++) {
                float v = p[tap];
                __half h = __float2half_rn(v);
                __half l = __float2half_rn(v - __half2float(h));
                size_t di = ((size_t)tap * COUT + o) * CIN + i;
                g_wh[di] = h;
                g_wl[di] = l;
            }
        }
    }
}

// ============================================================
// KP2: wsq (bid<512) + x modulate/transpose/fp16 (bid<8704)
// ============================================================
__global__ __launch_bounds__(512) void kp2(const float* __restrict__ x)
{
    int bid = blockIdx.x;
    if (bid < 512) {
        int i = bid, o = threadIdx.x;
        float s = 0.f;
#pragma unroll
        for (int tap = 0; tap < 9; tap++) {
            float v = g_cwt[(i * 9 + tap) * COUT + o];
            s += v * v;
        }
        g_wsqT[i * COUT + o] = s;
    } else {
        __shared__ float t[64][65];
        int q = bid - 512;
        int p0 = (q & 63) * 64;
        int i0 = ((q >> 6) & 7) * 64;
        int b  = q >> 9;
        for (int idx = threadIdx.x; idx < 4096; idx += 512) {
            int ii = idx >> 6, pp = idx & 63;
            t[ii][pp] = x[((size_t)b * CIN + i0 + ii) * NPIX + p0 + pp] *
                        g_mod[b * CIN + i0 + ii];
        }
        __syncthreads();
        for (int idx = threadIdx.x; idx < 4096; idx += 512) {
            int pp = idx >> 6, ii = idx & 63;
            g_xh[((size_t)b * NPIX + p0 + pp) * CIN + i0 + ii] =
                __float2half_rn(t[ii][pp]);
        }
    }
}

// ============================================================
// KP3: sigma_inv
// ============================================================
__global__ __launch_bounds__(512) void kp3()
{
    __shared__ float m2[CIN];
    int b = blockIdx.x, o = threadIdx.x;
    for (int i = threadIdx.x; i < CIN; i += 512) {
        float m = g_mod[b * CIN + i];
        m2[i] = m * m;
    }
    __syncthreads();
    float s = 0.f;
    for (int i = 0; i < CIN; i++) s += m2[i] * g_wsqT[i * COUT + o];
    g_sig[b * COUT + o] = 1.0f / sqrtf(s + 1e-8f);
}

// ============================================================
// K6: conv as fp16 2-pass split GEMM (A = wh+wl, B = fp16(x*mod)).
// CTA 128oc x 256px, 512 thr, warp grid 4(M)x4(N), warp tile 32oc x 64px.
// B: halo 6x66, single fp16 plane, DOUBLE buffered across ic chunks.
// A: per-(tap,ic) stage (2 planes), triple-buffered cp.async.
// ============================================================
#define BH_ROWS 6
#define BH_COLS 66
#define BH_PX   (BH_ROWS * BH_COLS)      // 396
#define BPL     (BH_PX * 128)            // 50688 per B buffer
#define A_STG   32768                    // per A stage (2 planes x 16KB)
#define B_OFF   (3 * A_STG)              // 98304
#define DSMEM   (B_OFF + 2 * BPL)        // 199680

#define MMA_F16(c, a, b0, b1)                                                \
    asm volatile("mma.sync.aligned.m16n8k16.row.col.f32.f16.f16.f32 "        \
        "{%0,%1,%2,%3}, {%4,%5,%6,%7}, {%8,%9}, {%0,%1,%2,%3};"              \
        : "+f"((c)[0]), "+f"((c)[1]), "+f"((c)[2]), "+f"((c)[3])             \
        : "r"((a)[0]), "r"((a)[1]), "r"((a)[2]), "r"((a)[3]),                \
          "r"(b0), "r"(b1))

#define LDSM4(r, addr)                                                       \
    asm volatile("ldmatrix.sync.aligned.m8n8.x4.shared.b16 "                 \
        "{%0,%1,%2,%3}, [%4];"                                               \
        : "=r"((r)[0]), "=r"((r)[1]), "=r"((r)[2]), "=r"((r)[3])             \
        : "r"(addr))

__global__ __launch_bounds__(512, 1) void k_conv_hmma(
    const float* __restrict__ noise, const float* __restrict__ scale_noise,
    const float* __restrict__ bias, float* __restrict__ out)
{
    extern __shared__ __align__(1024) char dsm[];
    uint32_t sbase = smem_u32(dsm);

    int tid = threadIdx.x;
    int lane = tid & 31, wid = tid >> 5;
    int wm = wid >> 2, wn = wid & 3;
    int b    = blockIdx.z;
    int oc0  = blockIdx.x * 128;
    int pix0 = blockIdx.y * 256;
    int pr0  = blockIdx.y * 4;

    // A ldmatrix lane components
    int selA = ((lane >> 4) & 1) * 16;
    uint32_t rbA[2], mkA[2];
#pragma unroll
    for (int mt = 0; mt < 2; mt++) {
        int row = wm * 32 + mt * 16 + (lane & 15);
        rbA[mt] = row * 128;
        mkA[mt] = (uint32_t)(row & 7) << 4;
    }
    // B lane pixel decomposition
    int selB = ((lane >> 3) & 1) * 16;
    int irB[4], icB[4];
#pragma unroll
    for (int j = 0; j < 4; j++) {
        int n = wn * 64 + j * 16 + (lane & 7) + ((lane >> 4) & 1) * 8;
        irB[j] = n >> 6;
        icB[j] = n & 63;
    }

    float acc[2][8][4];
#pragma unroll
    for (int mt = 0; mt < 2; mt++)
#pragma unroll
        for (int nt = 0; nt < 8; nt++)
#pragma unroll
            for (int q = 0; q < 4; q++) acc[mt][nt][q] = 0.f;

    auto load_A = [&](int tapv, int icv, int buf) {
#pragma unroll
        for (int k = 0; k < 4; k++) {
            int idx = tid + k * 512;
            int plane = idx >> 10;
            int rem = idx & 1023;
            int row = rem >> 3, cb = rem & 7;
            const __half* g = (plane ? g_wl : g_wh) +
                ((size_t)tapv * COUT + oc0 + row) * CIN + icv * 64 + cb * 8;
            uint32_t d = sbase + buf * A_STG + plane * 16384 +
                         (uint32_t)(row * 128) + (uint32_t)((cb * 16) ^ ((row & 7) << 4));
            asm volatile("cp.async.cg.shared.global [%0], [%1], 16;"
                         :: "r"(d), "l"(g));
        }
        asm volatile("cp.async.commit_group;");
    };

    auto load_B = [&](int icv, int buf) {
        for (int idx = tid; idx < BH_PX * 8; idx += 512) {
            int px = idx >> 3, cb = idx & 7;
            int hrow = px / BH_COLS;
            int hcol = px - hrow * BH_COLS;
            int r = pr0 - 1 + hrow;
            int c = hcol - 1;
            int ok = ((unsigned)r < Hs) && ((unsigned)c < Ws);
            const __half* g = g_xh +
                ((size_t)b * NPIX + (ok ? r * Ws + c : 0)) * CIN +
                icv * 64 + cb * 8;
            uint32_t d = sbase + B_OFF + buf * BPL + (uint32_t)(px * 128) +
                         (uint32_t)((cb * 16) ^ ((px & 7) << 4));
            int sz = ok ? 16 : 0;
            asm volatile("cp.async.cg.shared.global [%0], [%1], 16, %2;"
                         :: "r"(d), "l"(g), "r"(sz));
        }
        asm volatile("cp.async.commit_group;");
    };

    // prologue: A(0), B(0), A(1)
    load_A(0, 0, 0);
    load_B(0, 0);
    load_A(1, 0, 1);

    int s = 0;
    int ntap = 2, nic = 0;
    for (int ic = 0; ic < 8; ic++) {
        for (int tap = 0; tap < 9; tap++, s++) {
            // static wait schedule (see derivation): A prefetch distance 2,
            // B double-buffered, commits ordered A then B at tap0.
            if (s == 71)
                asm volatile("cp.async.wait_group 0;");
            else if ((tap == 1 || tap == 2) && ic < 7)
                asm volatile("cp.async.wait_group 2;");
            else
                asm volatile("cp.async.wait_group 1;");
            __syncthreads();

            if (s < 70) {
                load_A(ntap, nic, (s + 2) % 3);
                if (++ntap == 9) { ntap = 0; nic++; }
            }
            if (tap == 0 && ic < 7) load_B(ic + 1, (ic + 1) & 1);

            // ---- compute stage s ----
            uint32_t abuf = sbase + (s % 3) * A_STG;
            uint32_t bbuf = sbase + B_OFF + (ic & 1) * BPL;
            int dy = tap / 3 - 1, dx = tap % 3 - 1;
            uint32_t rowB[4], mskB[4];
#pragma unroll
            for (int j = 0; j < 4; j++) {
                int rp = (irB[j] + 1 + dy) * BH_COLS + icB[j] + 1 + dx;
                rowB[j] = (uint32_t)(rp * 128);
                mskB[j] = (uint32_t)(rp & 7) << 4;
            }

#pragma unroll
            for (int kk = 0; kk < 4; kk++) {
                int col = kk * 32;
                uint32_t aF[2][2][4];
#pragma unroll
                for (int pl = 0; pl < 2; pl++)
#pragma unroll
                    for (int mt = 0; mt < 2; mt++) {
                        uint32_t a = abuf + pl * 16384 + rbA[mt] +
                                     (uint32_t)((col + selA) ^ mkA[mt]);
                        LDSM4(aF[pl][mt], a);
                    }
                uint32_t bF[4][4];
#pragma unroll
                for (int j = 0; j < 4; j++) {
                    uint32_t a = bbuf + rowB[j] +
                                 (uint32_t)((col + selB) ^ mskB[j]);
                    LDSM4(bF[j], a);
                }
                // pass hh: Ah x B
#pragma unroll
                for (int mt = 0; mt < 2; mt++)
#pragma unroll
                    for (int nt = 0; nt < 8; nt++) {
                        int j = nt >> 1, lo = (nt & 1) * 2;
                        MMA_F16(acc[mt][nt], aF[0][mt], bF[j][lo], bF[j][lo + 1]);
                    }
                // pass lh: Al x B
#pragma unroll
                for (int mt = 0; mt < 2; mt++)
#pragma unroll
                    for (int nt = 0; nt < 8; nt++) {
                        int j = nt >> 1, lo = (nt & 1) * 2;
                        MMA_F16(acc[mt][nt], aF[1][mt], bF[j][lo], bF[j][lo + 1]);
                    }
            }
        }
    }

    // ---------------- epilogue ----------------
    float sn = __ldg(scale_noise);
#pragma unroll
    for (int mt = 0; mt < 2; mt++) {
        int oc_lo = oc0 + wm * 32 + mt * 16 + (lane >> 2);
        float sg0 = g_sig[b * COUT + oc_lo];
        float sg1 = g_sig[b * COUT + oc_lo + 8];
        float bi0 = __ldg(&bias[oc_lo]);
        float bi1 = __ldg(&bias[oc_lo + 8]);
#pragma unroll
        for (int nt = 0; nt < 8; nt++) {
            int p = pix0 + wn * 64 + nt * 8 + (lane & 3) * 2;
            float2 nz = *(const float2*)&noise[(size_t)b * NPIX + p];
            float n0 = sn * nz.x, n1 = sn * nz.y;

            float v0 = acc[mt][nt][0] * sg0 + n0 + bi0;
            float v1 = acc[mt][nt][1] * sg0 + n1 + bi0;
            float v2 = acc[mt][nt][2] * sg1 + n0 + bi1;
            float v3 = acc[mt][nt][3] * sg1 + n1 + bi1;
            v0 = v0 < 0.f ? 0.2f * v0 : v0;
            v1 = v1 < 0.f ? 0.2f * v1 : v1;
            v2 = v2 < 0.f ? 0.2f * v2 : v2;
            v3 = v3 < 0.f ? 0.2f * v3 : v3;

            *(float2*)&out[((size_t)(b * COUT + oc_lo)) * NPIX + p] =
                make_float2(v0, v1);
            *(float2*)&out[((size_t)(b * COUT + oc_lo + 8)) * NPIX + p] =
                make_float2(v2, v3);
        }
    }
}

// ============================================================
// launch: x, w, noise, style_w, style_b, conv_w, scale_noise, bias
// ============================================================
extern "C" void kernel_launch(void* const* d_in, const int* in_sizes, int n_in,
                              void* d_out, int out_size)
{
    const float* x           = (const float*)d_in[0];
    const float* w           = (const float*)d_in[1];
    const float* noise       = (const float*)d_in[2];
    const float* style_w     = (const float*)d_in[3];
    const float* style_b     = (const float*)d_in[4];
    const float* conv_w      = (const float*)d_in[5];
    const float* scale_noise = (const float*)d_in[6];
    const float* bias        = (const float*)d_in[7];
    float* out = (float*)d_out;

    cudaFuncSetAttribute(k_conv_hmma,
                         cudaFuncAttributeMaxDynamicSharedMemorySize, DSMEM);

    kp1<<<9760, 256>>>(w, style_w, style_b, conv_w);
    kp2<<<8704, 512>>>(x);
    kp3<<<16, 512>>>();
    k_conv_hmma<<<dim3(4, 16, B_), 512, DSMEM>>>(noise, scale_noise, bias, out);
}

// round 9
// speedup vs baseline: 2.2853x; 1.6198x over previous
#include <cuda_runtime.h>
#include <cuda_fp16.h>
#include <cstdint>

#define B_    16
#define CIN   512
#define COUT  512
#define DLAT  512
#define Hs    64
#define Ws    64
#define NPIX  (Hs*Ws)

#define LIN_COEF  0.04419417382415922f    // 1/sqrt(512)
#define CONV_COEF 0.014731391274719742f   // 1/sqrt(512*9)

// ---------------- device scratch (no allocation allowed) ----------------
__device__ float g_mod[B_ * CIN];
__device__ float g_sig[B_ * COUT];
__device__ float g_cwt[CIN * 9 * COUT];
__device__ float g_wsqT[CIN * COUT];
__device__ __half g_xh[(size_t)B_ * NPIX * CIN];   // NHWC, fp16(x*mod)
__device__ __half g_wh[9 * COUT * CIN];            // [tap][o][i] fp16

__device__ __forceinline__ uint32_t smem_u32(const void* p) {
    uint32_t a;
    asm("{ .reg .u64 t; cvta.to.shared.u64 t, %1; cvt.u32.u64 %0, t; }"
        : "=r"(a) : "l"(p));
    return a;
}

// ============================================================
// KP1: style (bid<32) + conv_w transpose (bid<9248) + w->fp16 (bid<9760)
// ============================================================
__global__ __launch_bounds__(256) void kp1(
    const float* __restrict__ w, const float* __restrict__ sw,
    const float* __restrict__ sb, const float* __restrict__ cw)
{
    int bid = blockIdx.x;
    if (bid < 32) {
        __shared__ float s_sw[16][DLAT + 1];
        int i0 = bid * 16;
        for (int idx = threadIdx.x; idx < 16 * DLAT; idx += 256) {
            int r = idx / DLAT, d = idx % DLAT;
            s_sw[r][d] = sw[(i0 + r) * DLAT + d];
        }
        __syncthreads();
        int t = threadIdx.x;
        int b = t >> 4, il = t & 15;
        const float* wb = w + b * DLAT;
        float acc = 0.f;
        for (int d = 0; d < DLAT; d++) acc += __ldg(&wb[d]) * s_sw[il][d];
        int i = i0 + il;
        g_mod[b * CIN + i] = (acc * LIN_COEF + sb[i]) * CONV_COEF;
    } else if (bid < 32 + 9216) {
        int e = (bid - 32) * 256 + threadIdx.x;       // (i, tap, o), o fastest
        int o = e & 511;
        int r = e >> 9;
        int tap = r % 9, i = r / 9;
        g_cwt[(i * 9 + tap) * COUT + o] = cw[(o * CIN + i) * 9 + tap];
    } else {
        int o = bid - 9248;
        for (int i = threadIdx.x; i < CIN; i += 256) {
            const float* p = cw + ((size_t)o * CIN + i) * 9;
#pragma unroll
            for (int tap = 0; tap < 9; tap++) {
                g_wh[((size_t)tap * COUT + o) * CIN + i] =
                    __float2half_rn(p[tap]);
            }
        }
    }
}

// ============================================================
// KP2: wsq (bid<512) + x modulate/transpose/fp16 (bid<8704)
// ============================================================
__global__ __launch_bounds__(512) void kp2(const float* __restrict__ x)
{
    int bid = blockIdx.x;
    if (bid < 512) {
        int i = bid, o = threadIdx.x;
        float s = 0.f;
#pragma unroll
        for (int tap = 0; tap < 9; tap++) {
            float v = g_cwt[(i * 9 + tap) * COUT + o];
            s += v * v;
        }
        g_wsqT[i * COUT + o] = s;
    } else {
        __shared__ float t[64][65];
        int q = bid - 512;
        int p0 = (q & 63) * 64;
        int i0 = ((q >> 6) & 7) * 64;
        int b  = q >> 9;
        for (int idx = threadIdx.x; idx < 4096; idx += 512) {
            int ii = idx >> 6, pp = idx & 63;
            t[ii][pp] = x[((size_t)b * CIN + i0 + ii) * NPIX + p0 + pp] *
                        g_mod[b * CIN + i0 + ii];
        }
        __syncthreads();
        for (int idx = threadIdx.x; idx < 4096; idx += 512) {
            int pp = idx >> 6, ii = idx & 63;
            g_xh[((size_t)b * NPIX + p0 + pp) * CIN + i0 + ii] =
                __float2half_rn(t[ii][pp]);
        }
    }
}

// ============================================================
// KP3: sigma_inv
// ============================================================
__global__ __launch_bounds__(512) void kp3()
{
    __shared__ float m2[CIN];
    int b = blockIdx.x, o = threadIdx.x;
    for (int i = threadIdx.x; i < CIN; i += 512) {
        float m = g_mod[b * CIN + i];
        m2[i] = m * m;
    }
    __syncthreads();
    float s = 0.f;
    for (int i = 0; i < CIN; i++) s += m2[i] * g_wsqT[i * COUT + o];
    g_sig[b * COUT + o] = 1.0f / sqrtf(s + 1e-8f);
}

// ============================================================
// K6: conv as single-pass fp16 GEMM (A = fp16(w), B = fp16(x*mod)).
// CTA 128oc x 256px, 512 thr, warp grid 4(M)x4(N), warp tile 32oc x 64px.
// B: halo 6x66 fp16, DOUBLE buffered across ic chunks.
// A: per-(tap,ic) stage 16KB, triple-buffered cp.async.
// ============================================================
#define BH_ROWS 6
#define BH_COLS 66
#define BH_PX   (BH_ROWS * BH_COLS)      // 396
#define BPL     (BH_PX * 128)            // 50688 per B buffer
#define A_STG   16384                    // per A stage (1 plane)
#define B_OFF   (3 * A_STG)              // 49152
#define DSMEM   (B_OFF + 2 * BPL)        // 150528

#define MMA_F16(c, a, b0, b1)                                                \
    asm volatile("mma.sync.aligned.m16n8k16.row.col.f32.f16.f16.f32 "        \
        "{%0,%1,%2,%3}, {%4,%5,%6,%7}, {%8,%9}, {%0,%1,%2,%3};"              \
        : "+f"((c)[0]), "+f"((c)[1]), "+f"((c)[2]), "+f"((c)[3])             \
        : "r"((a)[0]), "r"((a)[1]), "r"((a)[2]), "r"((a)[3]),                \
          "r"(b0), "r"(b1))

#define LDSM4(r, addr)                                                       \
    asm volatile("ldmatrix.sync.aligned.m8n8.x4.shared.b16 "                 \
        "{%0,%1,%2,%3}, [%4];"                                               \
        : "=r"((r)[0]), "=r"((r)[1]), "=r"((r)[2]), "=r"((r)[3])             \
        : "r"(addr))

__global__ __launch_bounds__(512, 1) void k_conv_hmma(
    const float* __restrict__ noise, const float* __restrict__ scale_noise,
    const float* __restrict__ bias, float* __restrict__ out)
{
    extern __shared__ __align__(1024) char dsm[];
    uint32_t sbase = smem_u32(dsm);

    int tid = threadIdx.x;
    int lane = tid & 31, wid = tid >> 5;
    int wm = wid >> 2, wn = wid & 3;
    int b    = blockIdx.z;
    int oc0  = blockIdx.x * 128;
    int pix0 = blockIdx.y * 256;
    int pr0  = blockIdx.y * 4;

    // A ldmatrix lane components
    int selA = ((lane >> 4) & 1) * 16;
    uint32_t rbA[2], mkA[2];
#pragma unroll
    for (int mt = 0; mt < 2; mt++) {
        int row = wm * 32 + mt * 16 + (lane & 15);
        rbA[mt] = row * 128;
        mkA[mt] = (uint32_t)(row & 7) << 4;
    }
    // B lane pixel decomposition
    int selB = ((lane >> 3) & 1) * 16;
    int irB[4], icB[4];
#pragma unroll
    for (int j = 0; j < 4; j++) {
        int n = wn * 64 + j * 16 + (lane & 7) + ((lane >> 4) & 1) * 8;
        irB[j] = n >> 6;
        icB[j] = n & 63;
    }

    float acc[2][8][4];
#pragma unroll
    for (int mt = 0; mt < 2; mt++)
#pragma unroll
        for (int nt = 0; nt < 8; nt++)
#pragma unroll
            for (int q = 0; q < 4; q++) acc[mt][nt][q] = 0.f;

    auto load_A = [&](int tapv, int icv, int buf) {
#pragma unroll
        for (int k = 0; k < 2; k++) {
            int idx = tid + k * 512;
            int row = idx >> 3, cb = idx & 7;
            const __half* g = g_wh +
                ((size_t)tapv * COUT + oc0 + row) * CIN + icv * 64 + cb * 8;
            uint32_t d = sbase + buf * A_STG +
                         (uint32_t)(row * 128) + (uint32_t)((cb * 16) ^ ((row & 7) << 4));
            asm volatile("cp.async.cg.shared.global [%0], [%1], 16;"
                         :: "r"(d), "l"(g));
        }
        asm volatile("cp.async.commit_group;");
    };

    auto load_B = [&](int icv, int buf) {
        for (int idx = tid; idx < BH_PX * 8; idx += 512) {
            int px = idx >> 3, cb = idx & 7;
            int hrow = px / BH_COLS;
            int hcol = px - hrow * BH_COLS;
            int r = pr0 - 1 + hrow;
            int c = hcol - 1;
            int ok = ((unsigned)r < Hs) && ((unsigned)c < Ws);
            const __half* g = g_xh +
                ((size_t)b * NPIX + (ok ? r * Ws + c : 0)) * CIN +
                icv * 64 + cb * 8;
            uint32_t d = sbase + B_OFF + buf * BPL + (uint32_t)(px * 128) +
                         (uint32_t)((cb * 16) ^ ((px & 7) << 4));
            int sz = ok ? 16 : 0;
            asm volatile("cp.async.cg.shared.global [%0], [%1], 16, %2;"
                         :: "r"(d), "l"(g), "r"(sz));
        }
        asm volatile("cp.async.commit_group;");
    };

    // prologue: A(0), B(0), A(1)
    load_A(0, 0, 0);
    load_B(0, 0);
    load_A(1, 0, 1);

    int s = 0;
    int ntap = 2, nic = 0;
    for (int ic = 0; ic < 8; ic++) {
        for (int tap = 0; tap < 9; tap++, s++) {
            // static wait schedule: A prefetch distance 2, B double-buffered,
            // commits ordered A then B at tap0.
            if (s == 71)
                asm volatile("cp.async.wait_group 0;");
            else if ((tap == 1 || tap == 2) && ic < 7)
                asm volatile("cp.async.wait_group 2;");
            else
                asm volatile("cp.async.wait_group 1;");
            __syncthreads();

            if (s < 70) {
                load_A(ntap, nic, (s + 2) % 3);
                if (++ntap == 9) { ntap = 0; nic++; }
            }
            if (tap == 0 && ic < 7) load_B(ic + 1, (ic + 1) & 1);

            // ---- compute stage s ----
            uint32_t abuf = sbase + (s % 3) * A_STG;
            uint32_t bbuf = sbase + B_OFF + (ic & 1) * BPL;
            int dy = tap / 3 - 1, dx = tap % 3 - 1;
            uint32_t rowB[4], mskB[4];
#pragma unroll
            for (int j = 0; j < 4; j++) {
                int rp = (irB[j] + 1 + dy) * BH_COLS + icB[j] + 1 + dx;
                rowB[j] = (uint32_t)(rp * 128);
                mskB[j] = (uint32_t)(rp & 7) << 4;
            }

#pragma unroll
            for (int kk = 0; kk < 4; kk++) {
                int col = kk * 32;
                uint32_t aF[2][4];
#pragma unroll
                for (int mt = 0; mt < 2; mt++) {
                    uint32_t a = abuf + rbA[mt] +
                                 (uint32_t)((col + selA) ^ mkA[mt]);
                    LDSM4(aF[mt], a);
                }
                uint32_t bF[4][4];
#pragma unroll
                for (int j = 0; j < 4; j++) {
                    uint32_t a = bbuf + rowB[j] +
                                 (uint32_t)((col + selB) ^ mskB[j]);
                    LDSM4(bF[j], a);
                }
#pragma unroll
                for (int mt = 0; mt < 2; mt++)
#pragma unroll
                    for (int nt = 0; nt < 8; nt++) {
                        int j = nt >> 1, lo = (nt & 1) * 2;
                        MMA_F16(acc[mt][nt], aF[mt], bF[j][lo], bF[j][lo + 1]);
                    }
            }
        }
    }

    // ---------------- epilogue ----------------
    float sn = __ldg(scale_noise);
#pragma unroll
    for (int mt = 0; mt < 2; mt++) {
        int oc_lo = oc0 + wm * 32 + mt * 16 + (lane >> 2);
        float sg0 = g_sig[b * COUT + oc_lo];
        float sg1 = g_sig[b * COUT + oc_lo + 8];
        float bi0 = __ldg(&bias[oc_lo]);
        float bi1 = __ldg(&bias[oc_lo + 8]);
#pragma unroll
        for (int nt = 0; nt < 8; nt++) {
            int p = pix0 + wn * 64 + nt * 8 + (lane & 3) * 2;
            float2 nz = *(const float2*)&noise[(size_t)b * NPIX + p];
            float n0 = sn * nz.x, n1 = sn * nz.y;

            float v0 = acc[mt][nt][0] * sg0 + n0 + bi0;
            float v1 = acc[mt][nt][1] * sg0 + n1 + bi0;
            float v2 = acc[mt][nt][2] * sg1 + n0 + bi1;
            float v3 = acc[mt][nt][3] * sg1 + n1 + bi1;
            v0 = v0 < 0.f ? 0.2f * v0 : v0;
            v1 = v1 < 0.f ? 0.2f * v1 : v1;
            v2 = v2 < 0.f ? 0.2f * v2 : v2;
            v3 = v3 < 0.f ? 0.2f * v3 : v3;

            *(float2*)&out[((size_t)(b * COUT + oc_lo)) * NPIX + p] =
                make_float2(v0, v1);
            *(float2*)&out[((size_t)(b * COUT + oc_lo + 8)) * NPIX + p] =
                make_float2(v2, v3);
        }
    }
}

// ============================================================
// launch: x, w, noise, style_w, style_b, conv_w, scale_noise, bias
// ============================================================
extern "C" void kernel_launch(void* const* d_in, const int* in_sizes, int n_in,
                              void* d_out, int out_size)
{
    const float* x           = (const float*)d_in[0];
    const float* w           = (const float*)d_in[1];
    const float* noise       = (const float*)d_in[2];
    const float* style_w     = (const float*)d_in[3];
    const float* style_b     = (const float*)d_in[4];
    const float* conv_w      = (const float*)d_in[5];
    const float* scale_noise = (const float*)d_in[6];
    const float* bias        = (const float*)d_in[7];
    float* out = (float*)d_out;

    cudaFuncSetAttribute(k_conv_hmma,
                         cudaFuncAttributeMaxDynamicSharedMemorySize, DSMEM);

    kp1<<<9760, 256>>>(w, style_w, style_b, conv_w);
    kp2<<<8704, 512>>>(x);
    kp3<<<16, 512>>>();
    k_conv_hmma<<<dim3(4, 16, B_), 512, DSMEM>>>(noise, scale_noise, bias, out);
}

// round 10
// speedup vs baseline: 2.5916x; 1.1341x over previous
#include <cuda_runtime.h>
#include <cuda_fp16.h>
#include <cstdint>

#define B_    16
#define CIN   512
#define COUT  512
#define DLAT  512
#define Hs    64
#define Ws    64
#define NPIX  (Hs*Ws)

#define LIN_COEF  0.04419417382415922f    // 1/sqrt(512)
#define CONV_COEF 0.014731391274719742f   // 1/sqrt(512*9)

// ---------------- device scratch (no allocation allowed) ----------------
__device__ float g_mod[B_ * CIN];
__device__ float g_sig[B_ * COUT];
__device__ float g_wsqT[CIN * COUT];               // [i][o]
__device__ __half g_xh[(size_t)B_ * NPIX * CIN];   // NHWC, fp16(x*mod)
__device__ __half g_wh[9 * COUT * CIN];            // [tap][o][i] fp16

__device__ __forceinline__ uint32_t smem_u32(const void* p) {
    uint32_t a;
    asm("{ .reg .u64 t; cvta.to.shared.u64 t, %1; cvt.u32.u64 %0, t; }"
        : "=r"(a) : "l"(p));
    return a;
}

// ============================================================
// KP1: style (bid<32) + wsq tiled-transpose (bid<288) + w->fp16 (bid<800)
// block 256
// ============================================================
__global__ __launch_bounds__(256) void kp1(
    const float* __restrict__ w, const float* __restrict__ sw,
    const float* __restrict__ sb, const float* __restrict__ cw)
{
    int bid = blockIdx.x;
    if (bid < 32) {
        __shared__ float s_sw[16][DLAT + 1];
        int i0 = bid * 16;
        for (int idx = threadIdx.x; idx < 16 * DLAT; idx += 256) {
            int r = idx / DLAT, d = idx % DLAT;
            s_sw[r][d] = sw[(i0 + r) * DLAT + d];
        }
        __syncthreads();
        int t = threadIdx.x;
        int b = t >> 4, il = t & 15;
        const float* wb = w + b * DLAT;
        float acc = 0.f;
        for (int d = 0; d < DLAT; d++) acc += __ldg(&wb[d]) * s_sw[il][d];
        int i = i0 + il;
        g_mod[b * CIN + i] = (acc * LIN_COEF + sb[i]) * CONV_COEF;
    } else if (bid < 288) {
        // wsqT[i][o] = sum_tap cw[o][i][tap]^2, 32x32 tile via smem
        __shared__ float sc[32][289];
        int q = bid - 32;
        int i0 = (q & 15) * 32;
        int o0 = (q >> 4) * 32;
        for (int idx = threadIdx.x; idx < 32 * 288; idx += 256) {
            int r = idx / 288, cc = idx - r * 288;
            sc[r][cc] = cw[(size_t)(o0 + r) * 4608 + i0 * 9 + cc];
        }
        __syncthreads();
        for (int idx = threadIdx.x; idx < 1024; idx += 256) {
            int oi = idx & 31, ii = idx >> 5;
            float s = 0.f;
#pragma unroll
            for (int tap = 0; tap < 9; tap++) {
                float v = sc[oi][ii * 9 + tap];
                s += v * v;
            }
            g_wsqT[(i0 + ii) * COUT + o0 + oi] = s;
        }
    } else {
        int o = bid - 288;
        for (int i = threadIdx.x; i < CIN; i += 256) {
            const float* p = cw + ((size_t)o * CIN + i) * 9;
#pragma unroll
            for (int tap = 0; tap < 9; tap++) {
                g_wh[((size_t)tap * COUT + o) * CIN + i] =
                    __float2half_rn(p[tap]);
            }
        }
    }
}

// ============================================================
// KP2: x modulate + CHW->HWC transpose + fp16, 8192 blocks x 512
// ============================================================
__global__ __launch_bounds__(512) void kp2(const float* __restrict__ x)
{
    __shared__ float t[64][65];
    int q = blockIdx.x;
    int p0 = (q & 63) * 64;
    int i0 = ((q >> 6) & 7) * 64;
    int b  = q >> 9;
    for (int idx = threadIdx.x; idx < 4096; idx += 512) {
        int ii = idx >> 6, pp = idx & 63;
        t[ii][pp] = x[((size_t)b * CIN + i0 + ii) * NPIX + p0 + pp] *
                    g_mod[b * CIN + i0 + ii];
    }
    __syncthreads();
    for (int idx = threadIdx.x; idx < 4096; idx += 512) {
        int pp = idx >> 6, ii = idx & 63;
        g_xh[((size_t)b * NPIX + p0 + pp) * CIN + i0 + ii] =
            __float2half_rn(t[ii][pp]);
    }
}

// ============================================================
// KP3: sigma_inv
// ============================================================
__global__ __launch_bounds__(512) void kp3()
{
    __shared__ float m2[CIN];
    int b = blockIdx.x, o = threadIdx.x;
    for (int i = threadIdx.x; i < CIN; i += 512) {
        float m = g_mod[b * CIN + i];
        m2[i] = m * m;
    }
    __syncthreads();
    float s = 0.f;
    for (int i = 0; i < CIN; i++) s += m2[i] * g_wsqT[i * COUT + o];
    g_sig[b * COUT + o] = 1.0f / sqrtf(s + 1e-8f);
}

// ============================================================
// K6: conv, single-pass fp16 HMMA GEMM.
// CTA 128oc x 256px, 512 thr, warp grid 4(M)x4(N), warp tile 32oc x 64px.
// K chunk = 128 ic per stage (2 swizzle panels of 64), 4 chunks x 9 taps
// = 36 stages. A: 32KB/stage, triple-buffered. B: halo 6x66 x 128ic
// (2 panels, 101KB), single buffer, resident for 9 taps.
// ============================================================
#define BH_ROWS 6
#define BH_COLS 66
#define BH_PX   (BH_ROWS * BH_COLS)      // 396
#define BPL     (BH_PX * 128)            // 50688 per panel
#define A_STG   32768                    // 2 panels x 16KB
#define B_OFF   (3 * A_STG)              // 98304
#define DSMEM   (B_OFF + 2 * BPL)        // 199680

#define MMA_F16(c, a, b0, b1)                                                \
    asm volatile("mma.sync.aligned.m16n8k16.row.col.f32.f16.f16.f32 "        \
        "{%0,%1,%2,%3}, {%4,%5,%6,%7}, {%8,%9}, {%0,%1,%2,%3};"              \
        : "+f"((c)[0]), "+f"((c)[1]), "+f"((c)[2]), "+f"((c)[3])             \
        : "r"((a)[0]), "r"((a)[1]), "r"((a)[2]), "r"((a)[3]),                \
          "r"(b0), "r"(b1))

#define LDSM4(r, addr)                                                       \
    asm volatile("ldmatrix.sync.aligned.m8n8.x4.shared.b16 "                 \
        "{%0,%1,%2,%3}, [%4];"                                               \
        : "=r"((r)[0]), "=r"((r)[1]), "=r"((r)[2]), "=r"((r)[3])             \
        : "r"(addr))

__global__ __launch_bounds__(512, 1) void k_conv_hmma(
    const float* __restrict__ noise, const float* __restrict__ scale_noise,
    const float* __restrict__ bias, float* __restrict__ out)
{
    extern __shared__ __align__(1024) char dsm[];
    uint32_t sbase = smem_u32(dsm);

    int tid = threadIdx.x;
    int lane = tid & 31, wid = tid >> 5;
    int wm = wid >> 2, wn = wid & 3;
    int b    = blockIdx.z;
    int oc0  = blockIdx.x * 128;
    int pix0 = blockIdx.y * 256;
    int pr0  = blockIdx.y * 4;

    // A ldmatrix lane components
    int selA = ((lane >> 4) & 1) * 16;
    uint32_t rbA[2], mkA[2];
#pragma unroll
    for (int mt = 0; mt < 2; mt++) {
        int row = wm * 32 + mt * 16 + (lane & 15);
        rbA[mt] = row * 128;
        mkA[mt] = (uint32_t)(row & 7) << 4;
    }
    // B lane pixel decomposition
    int selB = ((lane >> 3) & 1) * 16;
    int irB[4], icB[4];
#pragma unroll
    for (int j = 0; j < 4; j++) {
        int n = wn * 64 + j * 16 + (lane & 7) + ((lane >> 4) & 1) * 8;
        irB[j] = n >> 6;
        icB[j] = n & 63;
    }

    float acc[2][8][4];
#pragma unroll
    for (int mt = 0; mt < 2; mt++)
#pragma unroll
        for (int nt = 0; nt < 8; nt++)
#pragma unroll
            for (int q = 0; q < 4; q++) acc[mt][nt][q] = 0.f;

    // A stage: 128 rows x 256B (2 panels of 64 ic)
    auto load_A = [&](int tapv, int chv, int buf) {
#pragma unroll
        for (int k = 0; k < 4; k++) {
            int idx = tid + k * 512;
            int panel = idx >> 10;
            int rem = idx & 1023;
            int row = rem >> 3, cb = rem & 7;
            const __half* g = g_wh +
                ((size_t)tapv * COUT + oc0 + row) * CIN +
                chv * 128 + panel * 64 + cb * 8;
            uint32_t d = sbase + buf * A_STG + panel * 16384 +
                         (uint32_t)(row * 128) +
                         (uint32_t)((cb * 16) ^ ((row & 7) << 4));
            asm volatile("cp.async.cg.shared.global [%0], [%1], 16;"
                         :: "r"(d), "l"(g));
        }
        asm volatile("cp.async.commit_group;");
    };

    // B halo: 396 px x 256B (2 panels)
    auto load_B = [&](int chv) {
        for (int idx = tid; idx < BH_PX * 16; idx += 512) {
            int px = idx >> 4;
            int qq = idx & 15;
            int panel = qq >> 3, cb = qq & 7;
            int hrow = px / BH_COLS;
            int hcol = px - hrow * BH_COLS;
            int r = pr0 - 1 + hrow;
            int c = hcol - 1;
            int ok = ((unsigned)r < Hs) && ((unsigned)c < Ws);
            const __half* g = g_xh +
                ((size_t)b * NPIX + (ok ? r * Ws + c : 0)) * CIN +
                chv * 128 + panel * 64 + cb * 8;
            uint32_t d = sbase + B_OFF + panel * BPL + (uint32_t)(px * 128) +
                         (uint32_t)((cb * 16) ^ ((px & 7) << 4));
            int sz = ok ? 16 : 0;
            asm volatile("cp.async.cg.shared.global [%0], [%1], 16, %2;"
                         :: "r"(d), "l"(g), "r"(sz));
        }
        asm volatile("cp.async.commit_group;");
    };

    // prologue: B(0), A(0), A(1)
    load_B(0);
    load_A(0, 0, 0);
    load_A(1, 0, 1);

    int s = 0;
    int ntap = 2, nch = 0;
    for (int ch = 0; ch < 4; ch++) {
        for (int tap = 0; tap < 9; tap++, s++) {
            if (tap == 0 && ch > 0) {
                __syncthreads();              // all warps done with old B
                load_B(ch);
                if (s < 34) {
                    load_A(ntap, nch, (s + 2) % 3);
                    if (++ntap == 9) { ntap = 0; nch++; }
                }
                asm volatile("cp.async.wait_group 1;");   // drains B (+old A)
                __syncthreads();
            } else {
                if (s == 35)
                    asm volatile("cp.async.wait_group 0;");
                else
                    asm volatile("cp.async.wait_group 1;");
                __syncthreads();
                if (s < 34) {
                    load_A(ntap, nch, (s + 2) % 3);
                    if (++ntap == 9) { ntap = 0; nch++; }
                }
            }

            // ---- compute stage s ----
            uint32_t abuf = sbase + (s % 3) * A_STG;
            int dy = tap / 3 - 1, dx = tap % 3 - 1;
            uint32_t rowB[4], mskB[4];
#pragma unroll
            for (int j = 0; j < 4; j++) {
                int rp = (irB[j] + 1 + dy) * BH_COLS + icB[j] + 1 + dx;
                rowB[j] = (uint32_t)(rp * 128);
                mskB[j] = (uint32_t)(rp & 7) << 4;
            }

#pragma unroll
            for (int kk = 0; kk < 8; kk++) {
                int pn  = kk >> 2;
                int col = (kk & 3) * 32;
                uint32_t aF[2][4];
#pragma unroll
                for (int mt = 0; mt < 2; mt++) {
                    uint32_t a = abuf + pn * 16384 + rbA[mt] +
                                 (uint32_t)((col + selA) ^ mkA[mt]);
                    LDSM4(aF[mt], a);
                }
                uint32_t bF[4][4];
#pragma unroll
                for (int j = 0; j < 4; j++) {
                    uint32_t a = sbase + B_OFF + pn * BPL + rowB[j] +
                                 (uint32_t)((col + selB) ^ mskB[j]);
                    LDSM4(bF[j], a);
                }
#pragma unroll
                for (int mt = 0; mt < 2; mt++)
#pragma unroll
                    for (int nt = 0; nt < 8; nt++) {
                        int j = nt >> 1, lo = (nt & 1) * 2;
                        MMA_F16(acc[mt][nt], aF[mt], bF[j][lo], bF[j][lo + 1]);
                    }
            }
        }
    }

    // ---------------- epilogue ----------------
    float sn = __ldg(scale_noise);
#pragma unroll
    for (int mt = 0; mt < 2; mt++) {
        int oc_lo = oc0 + wm * 32 + mt * 16 + (lane >> 2);
        float sg0 = g_sig[b * COUT + oc_lo];
        float sg1 = g_sig[b * COUT + oc_lo + 8];
        float bi0 = __ldg(&bias[oc_lo]);
        float bi1 = __ldg(&bias[oc_lo + 8]);
#pragma unroll
        for (int nt = 0; nt < 8; nt++) {
            int p = pix0 + wn * 64 + nt * 8 + (lane & 3) * 2;
            float2 nz = *(const float2*)&noise[(size_t)b * NPIX + p];
            float n0 = sn * nz.x, n1 = sn * nz.y;

            float v0 = acc[mt][nt][0] * sg0 + n0 + bi0;
            float v1 = acc[mt][nt][1] * sg0 + n1 + bi0;
            float v2 = acc[mt][nt][2] * sg1 + n0 + bi1;
            float v3 = acc[mt][nt][3] * sg1 + n1 + bi1;
            v0 = v0 < 0.f ? 0.2f * v0 : v0;
            v1 = v1 < 0.f ? 0.2f * v1 : v1;
            v2 = v2 < 0.f ? 0.2f * v2 : v2;
            v3 = v3 < 0.f ? 0.2f * v3 : v3;

            *(float2*)&out[((size_t)(b * COUT + oc_lo)) * NPIX + p] =
                make_float2(v0, v1);
            *(float2*)&out[((size_t)(b * COUT + oc_lo + 8)) * NPIX + p] =
                make_float2(v2, v3);
        }
    }
}

// ============================================================
// launch: x, w, noise, style_w, style_b, conv_w, scale_noise, bias
// ============================================================
extern "C" void kernel_launch(void* const* d_in, const int* in_sizes, int n_in,
                              void* d_out, int out_size)
{
    const float* x           = (const float*)d_in[0];
    const float* w           = (const float*)d_in[1];
    const float* noise       = (const float*)d_in[2];
    const float* style_w     = (const float*)d_in[3];
    const float* style_b     = (const float*)d_in[4];
    const float* conv_w      = (const float*)d_in[5];
    const float* scale_noise = (const float*)d_in[6];
    const float* bias        = (const float*)d_in[7];
    float* out = (float*)d_out;

    cudaFuncSetAttribute(k_conv_hmma,
                         cudaFuncAttributeMaxDynamicSharedMemorySize, DSMEM);

    kp1<<<800, 256>>>(w, style_w, style_b, conv_w);
    kp2<<<8192, 512>>>(x);
    kp3<<<16, 512>>>();
    k_conv_hmma<<<dim3(4, 16, B_), 512, DSMEM>>>(noise, scale_noise, bias, out);
}